// round 3
// baseline (speedup 1.0000x reference)
#include <cuda_runtime.h>
#include <cuda_bf16.h>
#include <mma.h>

using namespace nvcuda;

typedef __nv_bfloat16 bf16;

#define BS_TOK 4096
#define DMODEL 1024
#define NMEM   32768
#define DKEY   256
#define DVAL   1024
#define TOPK   32
#define NCAND  64

// ------------------------------ scratch (device globals) ------------------------------
__device__ __align__(16) double g_qd[BS_TOK * DKEY];        // exact q
__device__ __align__(16) float  g_qn_hi[BS_TOK * DKEY];
__device__ __align__(16) float  g_qn_lo[BS_TOK * DKEY];
__device__ __align__(16) bf16   g_qb[BS_TOK * DKEY];
__device__ __align__(16) float  g_kn_hi[NMEM * DKEY];
__device__ __align__(16) float  g_kn_lo[NMEM * DKEY];
__device__ __align__(16) bf16   g_kb[NMEM * DKEY];
__device__ __align__(16) bf16   g_sims[(size_t)BS_TOK * NMEM];   // 256 MB
__device__ int   g_cand[BS_TOK * NCAND];
__device__ float g_w[BS_TOK * TOPK];
__device__ int   g_widx[BS_TOK * TOPK];
__device__ __align__(16) float g_memout[BS_TOK * DVAL];
__device__ __align__(16) bf16 g_xhi[BS_TOK * DMODEL];
__device__ __align__(16) bf16 g_xlo[BS_TOK * DMODEL];
__device__ __align__(16) bf16 g_wghi[DVAL * DMODEL];
__device__ __align__(16) bf16 g_wglo[DVAL * DMODEL];
__device__ __align__(16) bf16 g_wohi[DMODEL * DVAL];
__device__ __align__(16) bf16 g_wolo[DMODEL * DVAL];
__device__ __align__(16) bf16 g_hhi[BS_TOK * DVAL];
__device__ __align__(16) bf16 g_hlo[BS_TOK * DVAL];

// ------------------------------ compensated MAC (TwoProdFMA + Knuth TwoSum) ------------------------------
__device__ __forceinline__ void kmac(float a, float b, float& s, float& c) {
    float p  = __fmul_rn(a, b);
    float e  = __fmaf_rn(a, b, -p);         // exact product error
    float t  = __fadd_rn(s, p);
    float bv = __fadd_rn(t, -s);
    float e1 = __fadd_rn(s, -__fadd_rn(t, -bv));
    float e2 = __fadd_rn(p, -bv);
    s = t;
    c = __fadd_rn(c, __fadd_rn(e, __fadd_rn(e1, e2)));
}

// ------------------------------ split fp32 -> bf16 hi/lo ------------------------------
// WHICH: 0 = x, 2 = w_gate, 3 = w_out
template<int WHICH>
__global__ void split_kernel(const float* __restrict__ src) {
    constexpr int n = (WHICH == 0) ? BS_TOK * DMODEL
                    : (WHICH == 2) ? DVAL * DMODEL
                                   : DMODEL * DVAL;
    bf16* hi = (WHICH == 0) ? g_xhi : (WHICH == 2) ? g_wghi : g_wohi;
    bf16* lo = (WHICH == 0) ? g_xlo : (WHICH == 2) ? g_wglo : g_wolo;
    int i = blockIdx.x * blockDim.x + threadIdx.x;
    if (i >= n) return;
    float v = src[i];
    bf16 h = __float2bfloat16(v);
    hi[i] = h;
    lo[i] = __float2bfloat16(v - __bfloat162float(h));
}

// ------------------------------ exact q GEMM: q = x @ w_q^T (compensated fp32) ------------------------------
#define QTM 64
#define QTN 64
#define QTK 32

__global__ __launch_bounds__(256) void qexact_kernel(const float* __restrict__ x,
                                                     const float* __restrict__ wq) {
    __shared__ float sX[QTK][QTM + 4];
    __shared__ float sW[QTK][QTN + 4];
    int bt = blockIdx.y * QTM;
    int bq = blockIdx.x * QTN;
    int tid = threadIdx.x;
    int ty = tid >> 4;   // 0..15 token group
    int tx = tid & 15;   // 0..15 qdim group

    float s[4][4], c[4][4];
    #pragma unroll
    for (int i = 0; i < 4; i++)
        #pragma unroll
        for (int j = 0; j < 4; j++) { s[i][j] = 0.f; c[i][j] = 0.f; }

    for (int kc = 0; kc < DMODEL; kc += QTK) {
        #pragma unroll
        for (int rep = 0; rep < 2; rep++) {
            int idx = tid + rep * 256;       // 0..511
            int row = idx >> 3;              // 0..63
            int c4 = idx & 7;                // 0..7
            float4 v = *(const float4*)(x + (size_t)(bt + row) * DMODEL + kc + c4 * 4);
            sX[c4*4+0][row] = v.x; sX[c4*4+1][row] = v.y;
            sX[c4*4+2][row] = v.z; sX[c4*4+3][row] = v.w;
            float4 w = *(const float4*)(wq + (size_t)(bq + row) * DMODEL + kc + c4 * 4);
            sW[c4*4+0][row] = w.x; sW[c4*4+1][row] = w.y;
            sW[c4*4+2][row] = w.z; sW[c4*4+3][row] = w.w;
        }
        __syncthreads();
        #pragma unroll 4
        for (int k = 0; k < QTK; k++) {
            float4 rx = *(const float4*)&sX[k][ty * 4];
            float4 rw = *(const float4*)&sW[k][tx * 4];
            float ax[4] = {rx.x, rx.y, rx.z, rx.w};
            float bw[4] = {rw.x, rw.y, rw.z, rw.w};
            #pragma unroll
            for (int i = 0; i < 4; i++)
                #pragma unroll
                for (int j = 0; j < 4; j++)
                    kmac(ax[i], bw[j], s[i][j], c[i][j]);
        }
        __syncthreads();
    }

    #pragma unroll
    for (int i = 0; i < 4; i++)
        #pragma unroll
        for (int j = 0; j < 4; j++)
            g_qd[(size_t)(bt + ty*4 + i) * DKEY + (bq + tx*4 + j)] =
                (double)s[i][j] + (double)c[i][j];
}

// ------------------------------ normalize (fp64) ------------------------------
__global__ void qnorm_kernel() {
    int row = blockIdx.x * (blockDim.x >> 5) + (threadIdx.x >> 5);
    int lane = threadIdx.x & 31;
    if (row >= BS_TOK) return;
    const double* q = g_qd + (size_t)row * DKEY;
    double ss = 0.0;
    double v[8];
    #pragma unroll
    for (int i = 0; i < 8; i++) { v[i] = q[lane + i * 32]; ss += v[i] * v[i]; }
    #pragma unroll
    for (int o = 16; o; o >>= 1) ss += __shfl_xor_sync(0xffffffffu, ss, o);
    double inv = 1.0 / fmax(sqrt(ss), 1e-12);
    #pragma unroll
    for (int i = 0; i < 8; i++) {
        double qn = v[i] * inv;
        float hi = (float)qn;
        float lo = (float)(qn - (double)hi);
        size_t gi = (size_t)row * DKEY + lane + i * 32;
        g_qn_hi[gi] = hi;
        g_qn_lo[gi] = lo;
        g_qb[gi] = __float2bfloat16(hi);
    }
}

__global__ void knorm_kernel(const float* __restrict__ keys) {
    int row = blockIdx.x * (blockDim.x >> 5) + (threadIdx.x >> 5);
    int lane = threadIdx.x & 31;
    if (row >= NMEM) return;
    const float* k = keys + (size_t)row * DKEY;
    double ss = 0.0;
    double v[8];
    #pragma unroll
    for (int i = 0; i < 8; i++) { v[i] = (double)k[lane + i * 32]; ss += v[i] * v[i]; }
    #pragma unroll
    for (int o = 16; o; o >>= 1) ss += __shfl_xor_sync(0xffffffffu, ss, o);
    double inv = 1.0 / fmax(sqrt(ss), 1e-12);
    #pragma unroll
    for (int i = 0; i < 8; i++) {
        double kn = v[i] * inv;
        float hi = (float)kn;
        float lo = (float)(kn - (double)hi);
        size_t gi = (size_t)row * DKEY + lane + i * 32;
        g_kn_hi[gi] = hi;
        g_kn_lo[gi] = lo;
        g_kb[gi] = __float2bfloat16(hi);
    }
}

// ------------------------------ sims GEMM (bf16, preselect precision) ------------------------------
__global__ void sims_kernel() {
    constexpr int BM = 128, BN = 128, KC = 16;
    __shared__ bf16 sA[BM * KC];
    __shared__ bf16 sB[BN * KC];
    __shared__ __align__(16) float stage[8][16 * 16];

    int bm = blockIdx.y * BM;
    int bn = blockIdx.x * BN;
    int tid = threadIdx.x;
    int warp = tid >> 5, lane = tid & 31;
    int wr = warp >> 1;
    int wc = warp & 1;

    wmma::fragment<wmma::accumulator, 16, 16, 16, float> acc[2][4];
    #pragma unroll
    for (int i = 0; i < 2; i++)
        #pragma unroll
        for (int j = 0; j < 4; j++) wmma::fill_fragment(acc[i][j], 0.0f);

    int r = tid >> 1, h = (tid & 1) * 8;

    for (int kc = 0; kc < DKEY; kc += KC) {
        *(float4*)(sA + r * KC + h) = *(const float4*)(g_qb + (size_t)(bm + r) * DKEY + kc + h);
        *(float4*)(sB + r * KC + h) = *(const float4*)(g_kb + (size_t)(bn + r) * DKEY + kc + h);
        __syncthreads();
        wmma::fragment<wmma::matrix_a, 16, 16, 16, bf16, wmma::row_major> a[2];
        wmma::fragment<wmma::matrix_b, 16, 16, 16, bf16, wmma::col_major> b[4];
        #pragma unroll
        for (int i = 0; i < 2; i++) wmma::load_matrix_sync(a[i], sA + (wr * 32 + i * 16) * KC, KC);
        #pragma unroll
        for (int j = 0; j < 4; j++) wmma::load_matrix_sync(b[j], sB + (wc * 64 + j * 16) * KC, KC);
        #pragma unroll
        for (int i = 0; i < 2; i++)
            #pragma unroll
            for (int j = 0; j < 4; j++) wmma::mma_sync(acc[i][j], a[i], b[j], acc[i][j]);
        __syncthreads();
    }

    float* st = stage[warp];
    int srow = lane >> 1, scol = (lane & 1) * 8;
    #pragma unroll
    for (int i = 0; i < 2; i++) {
        #pragma unroll
        for (int j = 0; j < 4; j++) {
            wmma::store_matrix_sync(st, acc[i][j], 16, wmma::mem_row_major);
            __syncwarp();
            __align__(16) bf16 tmp[8];
            #pragma unroll
            for (int e = 0; e < 8; e++) tmp[e] = __float2bfloat16(st[srow * 16 + scol + e]);
            size_t go = (size_t)(bm + wr * 32 + i * 16 + srow) * NMEM + (bn + wc * 64 + j * 16 + scol);
            *(float4*)(g_sims + go) = *(float4*)tmp;
            __syncwarp();
        }
    }
}

// ------------------------------ top-64 preselect (2-level radix on bf16 bits) ------------------------------
__device__ __forceinline__ unsigned ordkey16(unsigned u) {
    return (u & 0x8000u) ? (u ^ 0xFFFFu) : (u | 0x8000u);
}

__global__ void topk_kernel() {
    int t = blockIdx.x;
    const unsigned short* row = (const unsigned short*)(g_sims + (size_t)t * NMEM);
    __shared__ unsigned hist[256];
    __shared__ unsigned sh_b, sh_above, sh_K1, sh_thr;
    __shared__ unsigned ctrG, ctrE;
    int tid = threadIdx.x;

    hist[tid] = 0;
    __syncthreads();
    for (int i = tid; i < NMEM; i += 256) {
        unsigned k = ordkey16((unsigned)row[i]);
        atomicAdd(&hist[k >> 8], 1u);
    }
    __syncthreads();
    if (tid == 0) {
        unsigned cum = 0; int b = 255;
        for (; b > 0; b--) { if (cum + hist[b] >= NCAND) break; cum += hist[b]; }
        sh_b = (unsigned)b; sh_above = cum;
    }
    __syncthreads();
    unsigned b = sh_b, above = sh_above;
    hist[tid] = 0;
    __syncthreads();
    for (int i = tid; i < NMEM; i += 256) {
        unsigned k = ordkey16((unsigned)row[i]);
        if ((k >> 8) == b) atomicAdd(&hist[k & 255u], 1u);
    }
    __syncthreads();
    if (tid == 0) {
        unsigned cum = above; int l = 255;
        for (; l > 0; l--) { if (cum + hist[l] >= NCAND) break; cum += hist[l]; }
        sh_thr = (b << 8) | (unsigned)l;
        sh_K1 = cum;
        ctrG = 0; ctrE = 0;
    }
    __syncthreads();
    unsigned thr = sh_thr, K1 = sh_K1;
    for (int i = tid; i < NMEM; i += 256) {
        unsigned k = ordkey16((unsigned)row[i]);
        if (k > thr) {
            unsigned p = atomicAdd(&ctrG, 1u);
            g_cand[t * NCAND + p] = i;
        } else if (k == thr) {
            unsigned p = atomicAdd(&ctrE, 1u);
            if (K1 + p < NCAND) g_cand[t * NCAND + K1 + p] = i;
        }
    }
}

// ------------------------------ exact double-float rescore + top-32 + softmax ------------------------------
__global__ __launch_bounds__(256) void rescore_kernel() {
    int t = blockIdx.x;
    int tid = threadIdx.x;  // 256
    __shared__ __align__(16) float qhi[DKEY];
    __shared__ __align__(16) float qlo[DKEY];
    __shared__ float cval[NCAND];
    __shared__ int cidx[NCAND];
    __shared__ float sval[TOPK];
    __shared__ int sidx[TOPK];

    qhi[tid] = g_qn_hi[(size_t)t * DKEY + tid];
    qlo[tid] = g_qn_lo[(size_t)t * DKEY + tid];
    if (tid < NCAND) cidx[tid] = g_cand[t * NCAND + tid];
    __syncthreads();

    int c = tid >> 2, part = tid & 3;       // 64 cands x 4 quarters of 64 dims
    int ki = cidx[c];
    const float* khi = g_kn_hi + (size_t)ki * DKEY + part * 64;
    const float* klo = g_kn_lo + (size_t)ki * DKEY + part * 64;
    const float* qh = qhi + part * 64;
    const float* ql = qlo + part * 64;

    float s = 0.f, comp = 0.f, cr = 0.f;
    #pragma unroll 8
    for (int i = 0; i < 64; i++) {
        float kh = khi[i], kl = klo[i];
        float qhv = qh[i], qlv = ql[i];
        kmac(qhv, kh, s, comp);
        cr = __fmaf_rn(qhv, kl, cr);
        cr = __fmaf_rn(qlv, kh, cr);
    }
    double v = (double)s + (double)comp + (double)cr;
    v += __shfl_xor_sync(0xffffffffu, v, 1);
    v += __shfl_xor_sync(0xffffffffu, v, 2);
    if (part == 0) cval[c] = (float)v;   // fp32 rounding: mimic reference fp32 sims
    __syncthreads();

    if (tid < NCAND) {
        float val = cval[tid]; int myi = cidx[tid];
        int rnk = 0;
        #pragma unroll 8
        for (int j = 0; j < NCAND; j++) {
            float u = cval[j];
            rnk += (u > val) || (u == val && cidx[j] < myi);
        }
        if (rnk < TOPK) { sval[rnk] = val; sidx[rnk] = myi; }
    }
    __syncthreads();

    if (tid < 32) {
        float val = sval[tid];
        float m = val;
        #pragma unroll
        for (int o = 16; o; o >>= 1) m = fmaxf(m, __shfl_xor_sync(0xffffffffu, m, o));
        float e = expf(val - m);
        float sum = e;
        #pragma unroll
        for (int o = 16; o; o >>= 1) sum += __shfl_xor_sync(0xffffffffu, sum, o);
        g_w[t * TOPK + tid] = e / sum;
        g_widx[t * TOPK + tid] = sidx[tid];
    }
}

// ------------------------------ weighted values gather ------------------------------
__global__ void gather_kernel(const float* __restrict__ values) {
    int t = blockIdx.x, tid = threadIdx.x;  // 256
    __shared__ float w[TOPK];
    __shared__ int idx[TOPK];
    if (tid < TOPK) { w[tid] = g_w[t * TOPK + tid]; idx[tid] = g_widx[t * TOPK + tid]; }
    __syncthreads();
    float4 acc = make_float4(0.f, 0.f, 0.f, 0.f);
    #pragma unroll 8
    for (int i = 0; i < TOPK; i++) {
        const float4 v = *((const float4*)(values + (size_t)idx[i] * DVAL) + tid);
        float wi = w[i];
        acc.x = fmaf(wi, v.x, acc.x);
        acc.y = fmaf(wi, v.y, acc.y);
        acc.z = fmaf(wi, v.z, acc.z);
        acc.w = fmaf(wi, v.w, acc.w);
    }
    ((float4*)(g_memout + (size_t)t * DVAL))[tid] = acc;
}

// ------------------------------ 3-term split-bf16 GEMM (gate / out) ------------------------------
// WHICH: 1 = gate (A=x, B=w_gate, N=1024, K=1024, epilogue silu*memout -> h hi/lo)
//        2 = out  (A=h, B=w_out,  N=1024, K=1024, store fp32 -> Cout)
template<int WHICH>
__global__ void gemm_kernel(float* __restrict__ Cout) {
    constexpr int N = (WHICH == 1) ? DVAL : DMODEL;
    constexpr int K = (WHICH == 2) ? DVAL : DMODEL;
    constexpr int BM = 128, BN = 64, KC = 16;

    const bf16* Ahi = (WHICH == 2) ? g_hhi : g_xhi;
    const bf16* Alo = (WHICH == 2) ? g_hlo : g_xlo;
    const bf16* Bhi = (WHICH == 1) ? g_wghi : g_wohi;
    const bf16* Blo = (WHICH == 1) ? g_wglo : g_wolo;

    extern __shared__ char smem_raw[];
    bf16* sAhi = (bf16*)smem_raw;
    bf16* sAlo = sAhi + BM * KC;
    bf16* sBhi = sAlo + BM * KC;
    bf16* sBlo = sBhi + BN * KC;
    float* stage = (float*)(sBlo + BN * KC);  // 128*68, MODE 1 only

    int bm = blockIdx.y * BM;
    int bn = blockIdx.x * BN;
    int tid = threadIdx.x;
    int warp = tid >> 5;
    int wr = warp >> 1;
    int wc = warp & 1;

    wmma::fragment<wmma::accumulator, 16, 16, 16, float> acc[2][2];
    #pragma unroll
    for (int i = 0; i < 2; i++)
        #pragma unroll
        for (int j = 0; j < 2; j++) wmma::fill_fragment(acc[i][j], 0.0f);

    int ar = tid >> 1, ah = (tid & 1) * 8;
    int br = (tid & 127) >> 1, bh2 = (tid & 1) * 8;

    for (int kc = 0; kc < K; kc += KC) {
        *(float4*)(sAhi + ar * KC + ah) = *(const float4*)(Ahi + (size_t)(bm + ar) * K + kc + ah);
        *(float4*)(sAlo + ar * KC + ah) = *(const float4*)(Alo + (size_t)(bm + ar) * K + kc + ah);
        if (tid < 128) {
            *(float4*)(sBhi + br * KC + bh2) = *(const float4*)(Bhi + (size_t)(bn + br) * K + kc + bh2);
            *(float4*)(sBlo + br * KC + bh2) = *(const float4*)(Blo + (size_t)(bn + br) * K + kc + bh2);
        }
        __syncthreads();

        wmma::fragment<wmma::matrix_a, 16, 16, 16, bf16, wmma::row_major> a0, a1, c0, c1;
        wmma::fragment<wmma::matrix_b, 16, 16, 16, bf16, wmma::col_major> b0, b1;

        wmma::load_matrix_sync(a0, sAhi + (wr * 32 + 0) * KC, KC);
        wmma::load_matrix_sync(a1, sAhi + (wr * 32 + 16) * KC, KC);
        wmma::load_matrix_sync(b0, sBhi + (wc * 32 + 0) * KC, KC);
        wmma::load_matrix_sync(b1, sBhi + (wc * 32 + 16) * KC, KC);
        wmma::mma_sync(acc[0][0], a0, b0, acc[0][0]);
        wmma::mma_sync(acc[0][1], a0, b1, acc[0][1]);
        wmma::mma_sync(acc[1][0], a1, b0, acc[1][0]);
        wmma::mma_sync(acc[1][1], a1, b1, acc[1][1]);

        wmma::load_matrix_sync(c0, sAlo + (wr * 32 + 0) * KC, KC);
        wmma::load_matrix_sync(c1, sAlo + (wr * 32 + 16) * KC, KC);
        wmma::mma_sync(acc[0][0], c0, b0, acc[0][0]);
        wmma::mma_sync(acc[0][1], c0, b1, acc[0][1]);
        wmma::mma_sync(acc[1][0], c1, b0, acc[1][0]);
        wmma::mma_sync(acc[1][1], c1, b1, acc[1][1]);

        wmma::load_matrix_sync(b0, sBlo + (wc * 32 + 0) * KC, KC);
        wmma::load_matrix_sync(b1, sBlo + (wc * 32 + 16) * KC, KC);
        wmma::mma_sync(acc[0][0], a0, b0, acc[0][0]);
        wmma::mma_sync(acc[0][1], a0, b1, acc[0][1]);
        wmma::mma_sync(acc[1][0], a1, b0, acc[1][0]);
        wmma::mma_sync(acc[1][1], a1, b1, acc[1][1]);

        __syncthreads();
    }

    if (WHICH == 2) {
        #pragma unroll
        for (int i = 0; i < 2; i++)
            #pragma unroll
            for (int j = 0; j < 2; j++)
                wmma::store_matrix_sync(Cout + (size_t)(bm + wr * 32 + i * 16) * N + bn + wc * 32 + j * 16,
                                        acc[i][j], N, wmma::mem_row_major);
    } else {
        #pragma unroll
        for (int i = 0; i < 2; i++)
            #pragma unroll
            for (int j = 0; j < 2; j++)
                wmma::store_matrix_sync(stage + (wr * 32 + i * 16) * 68 + wc * 32 + j * 16,
                                        acc[i][j], 68, wmma::mem_row_major);
        __syncthreads();
        for (int e = tid; e < BM * BN; e += 256) {
            int lr = e >> 6, lc = e & 63;
            float gpre = stage[lr * 68 + lc];
            float sg = gpre / (1.0f + expf(-gpre));
            size_t gi = (size_t)(bm + lr) * N + bn + lc;
            float h = sg * g_memout[gi];
            bf16 hh = __float2bfloat16(h);
            g_hhi[gi] = hh;
            g_hlo[gi] = __float2bfloat16(h - __bfloat162float(hh));
        }
    }
}

// ------------------------------ launcher ------------------------------
extern "C" void kernel_launch(void* const* d_in, const int* in_sizes, int n_in,
                              void* d_out, int out_size) {
    const float *x = nullptr, *keys = nullptr, *values = nullptr,
                *w_q = nullptr, *w_gate = nullptr, *w_out = nullptr;
    for (int i = 0; i < n_in; i++) {
        int sz = in_sizes[i];
        const float* p = (const float*)d_in[i];
        if (sz == BS_TOK * DMODEL)      x = p;
        else if (sz == NMEM * DKEY)     keys = p;
        else if (sz == NMEM * DVAL)     values = p;
        else if (sz == DKEY * DMODEL)   w_q = p;
        else if (sz == DVAL * DMODEL) { if (!w_gate) w_gate = p; else w_out = p; }
    }
    float* out = (float*)d_out;

    // splits for gate/out GEMMs
    split_kernel<0><<<(BS_TOK * DMODEL + 255) / 256, 256>>>(x);
    split_kernel<2><<<(DVAL * DMODEL + 255) / 256, 256>>>(w_gate);
    split_kernel<3><<<(DMODEL * DVAL + 255) / 256, 256>>>(w_out);

    // normalize keys (exact, fp64)
    knorm_kernel<<<(NMEM + 7) / 8, 256>>>(keys);

    // exact q = x @ w_q^T (compensated fp32)
    qexact_kernel<<<dim3(DKEY / QTN, BS_TOK / QTM), 256>>>(x, w_q);

    // normalize q (exact, fp64)
    qnorm_kernel<<<(BS_TOK + 7) / 8, 256>>>();

    // sims (bf16 preselect)
    sims_kernel<<<dim3(NMEM / 128, BS_TOK / 128), 256>>>();

    // top-64 preselect
    topk_kernel<<<BS_TOK, 256>>>();

    // exact rescore + top-32 + softmax
    rescore_kernel<<<BS_TOK, 256>>>();

    // mem_out gather
    gather_kernel<<<BS_TOK, 256>>>(values);

    size_t smem_g = (size_t)(128 * 16 + 128 * 16 + 64 * 16 + 64 * 16) * sizeof(bf16);
    size_t smem_g1 = smem_g + (size_t)128 * 68 * sizeof(float);

    // gate = silu(x @ w_gate^T); h = gate * mem_out -> h hi/lo
    gemm_kernel<1><<<dim3(DVAL / 64, BS_TOK / 128), 256, smem_g1>>>(nullptr);

    // out = h @ w_out^T -> d_out
    gemm_kernel<2><<<dim3(DMODEL / 64, BS_TOK / 128), 256, smem_g>>>(out);
}

// round 4
// speedup vs baseline: 1.1846x; 1.1846x over previous
#include <cuda_runtime.h>
#include <cuda_bf16.h>
#include <mma.h>

using namespace nvcuda;

typedef __nv_bfloat16 bf16;

#define BS_TOK 4096
#define DMODEL 1024
#define NMEM   32768
#define DKEY   256
#define DVAL   1024
#define TOPK   32
#define NCAND  64

// ------------------------------ scratch (device globals) ------------------------------
__device__ __align__(16) float2 g_q2[BS_TOK * DKEY];        // exact q as (hi,lo)
__device__ __align__(16) float  g_qn_hi[BS_TOK * DKEY];
__device__ __align__(16) float  g_qn_lo[BS_TOK * DKEY];
__device__ __align__(16) bf16   g_qb[BS_TOK * DKEY];
__device__ __align__(16) float  g_kn_hi[NMEM * DKEY];
__device__ __align__(16) float  g_kn_lo[NMEM * DKEY];
__device__ __align__(16) bf16   g_kb[NMEM * DKEY];
__device__ __align__(16) bf16   g_sims[(size_t)BS_TOK * NMEM];   // 256 MB
__device__ int   g_cand[BS_TOK * NCAND];
__device__ float g_w[BS_TOK * TOPK];
__device__ int   g_widx[BS_TOK * TOPK];
__device__ __align__(16) float g_memout[BS_TOK * DVAL];
__device__ __align__(16) bf16 g_xhi[BS_TOK * DMODEL];
__device__ __align__(16) bf16 g_xlo[BS_TOK * DMODEL];
__device__ __align__(16) bf16 g_wghi[DVAL * DMODEL];
__device__ __align__(16) bf16 g_wglo[DVAL * DMODEL];
__device__ __align__(16) bf16 g_wohi[DMODEL * DVAL];
__device__ __align__(16) bf16 g_wolo[DMODEL * DVAL];
__device__ __align__(16) bf16 g_hhi[BS_TOK * DVAL];
__device__ __align__(16) bf16 g_hlo[BS_TOK * DVAL];

// ------------------------------ merged split fp32 -> bf16 hi/lo ------------------------------
#define NX (BS_TOK * DMODEL)
#define NWG (DVAL * DMODEL)
#define NWO (DMODEL * DVAL)

__global__ void splitall_kernel(const float* __restrict__ x,
                                const float* __restrict__ wg,
                                const float* __restrict__ wo) {
    int i = blockIdx.x * blockDim.x + threadIdx.x;
    const float* src; bf16 *hi, *lo; int j;
    if (i < NX) { src = x; hi = g_xhi; lo = g_xlo; j = i; }
    else if (i < NX + NWG) { src = wg; hi = g_wghi; lo = g_wglo; j = i - NX; }
    else if (i < NX + NWG + NWO) { src = wo; hi = g_wohi; lo = g_wolo; j = i - NX - NWG; }
    else return;
    float v = src[j];
    bf16 h = __float2bfloat16(v);
    hi[j] = h;
    lo[j] = __float2bfloat16(__fadd_rn(v, -__bfloat162float(h)));
}

// ------------------------------ key normalize (double-float fp32) ------------------------------
__global__ __launch_bounds__(256) void knorm_kernel(const float* __restrict__ keys) {
    int row = blockIdx.x * 8 + (threadIdx.x >> 5);
    int lane = threadIdx.x & 31;
    const float4* s4 = (const float4*)(keys + (size_t)row * DKEY);
    float4 a = s4[lane], b = s4[lane + 32];
    float v[8] = {a.x, a.y, a.z, a.w, b.x, b.y, b.z, b.w};

    float s = 0.f, c = 0.f;
    #pragma unroll
    for (int i = 0; i < 8; i++) {
        float p = __fmul_rn(v[i], v[i]);
        float e = __fmaf_rn(v[i], v[i], -p);
        float t  = __fadd_rn(s, p);
        float bv = __fadd_rn(t, -s);
        float err = __fadd_rn(__fadd_rn(s, -__fadd_rn(t, -bv)), __fadd_rn(p, -bv));
        s = t;
        c = __fadd_rn(c, __fadd_rn(err, e));
    }
    double d = (double)s + (double)c;
    #pragma unroll
    for (int o = 16; o; o >>= 1) d += __shfl_xor_sync(0xffffffffu, d, o);
    double inv = 1.0 / fmax(sqrt(d), 1e-12);
    float ih = (float)inv;
    float il = (float)(inv - (double)ih);

    float h2[8], l2[8];
    #pragma unroll
    for (int i = 0; i < 8; i++) {
        float p = __fmul_rn(v[i], ih);
        float e = __fmaf_rn(v[i], ih, -p);
        float lo = __fmaf_rn(v[i], il, e);
        float hh = __fadd_rn(p, lo);
        h2[i] = hh;
        l2[i] = __fadd_rn(lo, -__fadd_rn(hh, -p));
    }
    float4* dh = (float4*)(g_kn_hi + (size_t)row * DKEY);
    float4* dl = (float4*)(g_kn_lo + (size_t)row * DKEY);
    dh[lane]      = make_float4(h2[0], h2[1], h2[2], h2[3]);
    dh[lane + 32] = make_float4(h2[4], h2[5], h2[6], h2[7]);
    dl[lane]      = make_float4(l2[0], l2[1], l2[2], l2[3]);
    dl[lane + 32] = make_float4(l2[4], l2[5], l2[6], l2[7]);
    __nv_bfloat162* db = (__nv_bfloat162*)(g_kb + (size_t)row * DKEY);
    db[lane*2 + 0]  = __nv_bfloat162(__float2bfloat16(h2[0]), __float2bfloat16(h2[1]));
    db[lane*2 + 1]  = __nv_bfloat162(__float2bfloat16(h2[2]), __float2bfloat16(h2[3]));
    db[64 + lane*2 + 0] = __nv_bfloat162(__float2bfloat16(h2[4]), __float2bfloat16(h2[5]));
    db[64 + lane*2 + 1] = __nv_bfloat162(__float2bfloat16(h2[6]), __float2bfloat16(h2[7]));
}

// ------------------------------ exact q GEMM: q = x @ w_q^T (offset-accumulator, 7 ops/MAC) ------------------------------
#define QTM 64
#define QTN 64
#define QTK 32
#define QOFF 1024.0f

__global__ __launch_bounds__(256) void qexact_kernel(const float* __restrict__ x,
                                                     const float* __restrict__ wq) {
    __shared__ float sX[QTK][QTM + 4];
    __shared__ float sW[QTK][QTN + 4];
    int bt = blockIdx.y * QTM;
    int bq = blockIdx.x * QTN;
    int tid = threadIdx.x;
    int ty = tid >> 4;
    int tx = tid & 15;

    float A[4][4], A2[4][4];
    #pragma unroll
    for (int i = 0; i < 4; i++)
        #pragma unroll
        for (int j = 0; j < 4; j++) { A[i][j] = QOFF; A2[i][j] = 0.f; }

    for (int kc = 0; kc < DMODEL; kc += QTK) {
        #pragma unroll
        for (int rep = 0; rep < 2; rep++) {
            int idx = tid + rep * 256;
            int row = idx >> 3;
            int c4 = idx & 7;
            float4 v = *(const float4*)(x + (size_t)(bt + row) * DMODEL + kc + c4 * 4);
            sX[c4*4+0][row] = v.x; sX[c4*4+1][row] = v.y;
            sX[c4*4+2][row] = v.z; sX[c4*4+3][row] = v.w;
            float4 w = *(const float4*)(wq + (size_t)(bq + row) * DMODEL + kc + c4 * 4);
            sW[c4*4+0][row] = w.x; sW[c4*4+1][row] = w.y;
            sW[c4*4+2][row] = w.z; sW[c4*4+3][row] = w.w;
        }
        __syncthreads();
        #pragma unroll 4
        for (int k = 0; k < QTK; k++) {
            float4 rx = *(const float4*)&sX[k][ty * 4];
            float4 rw = *(const float4*)&sW[k][tx * 4];
            float ax[4] = {rx.x, rx.y, rx.z, rx.w};
            float bw[4] = {rw.x, rw.y, rw.z, rw.w};
            #pragma unroll
            for (int i = 0; i < 4; i++)
                #pragma unroll
                for (int j = 0; j < 4; j++) {
                    float p = __fmul_rn(ax[i], bw[j]);
                    float e = __fmaf_rn(ax[i], bw[j], -p);
                    float t = __fadd_rn(A[i][j], p);       // |A|>=|p| -> Fast2Sum exact
                    float z = __fadd_rn(t, -A[i][j]);
                    float r = __fadd_rn(p, -z);
                    A[i][j] = t;
                    A2[i][j] = __fadd_rn(A2[i][j], __fadd_rn(r, e));
                }
        }
        __syncthreads();
    }

    #pragma unroll
    for (int i = 0; i < 4; i++)
        #pragma unroll
        for (int j = 0; j < 4; j++) {
            double sum = (double)__fadd_rn(A[i][j], -QOFF) + (double)A2[i][j];
            float hi = (float)sum;
            float lo = (float)(sum - (double)hi);
            g_q2[(size_t)(bt + ty*4 + i) * DKEY + (bq + tx*4 + j)] = make_float2(hi, lo);
        }
}

// ------------------------------ q normalize (fp64, small) ------------------------------
__global__ void qnorm_kernel() {
    int row = blockIdx.x * 8 + (threadIdx.x >> 5);
    int lane = threadIdx.x & 31;
    const float2* q = g_q2 + (size_t)row * DKEY;
    double v[8];
    double ss = 0.0;
    #pragma unroll
    for (int i = 0; i < 8; i++) {
        float2 p = q[lane + i * 32];
        v[i] = (double)p.x + (double)p.y;
        ss = fma(v[i], v[i], ss);
    }
    #pragma unroll
    for (int o = 16; o; o >>= 1) ss += __shfl_xor_sync(0xffffffffu, ss, o);
    double inv = 1.0 / fmax(sqrt(ss), 1e-12);
    #pragma unroll
    for (int i = 0; i < 8; i++) {
        double qn = v[i] * inv;
        float hi = (float)qn;
        float lo = (float)(qn - (double)hi);
        size_t gi = (size_t)row * DKEY + lane + i * 32;
        g_qn_hi[gi] = hi;
        g_qn_lo[gi] = lo;
        g_qb[gi] = __float2bfloat16(hi);
    }
}

// ------------------------------ sims GEMM: full-K in smem, 128x256 tile ------------------------------
#define SBM 128
#define SBN 256
#define SPAD 264
#define SIMS_SMEM ((SBM * SPAD + SBN * SPAD) * 2)

__global__ __launch_bounds__(256, 1) void sims_kernel() {
    extern __shared__ char smem_raw[];
    bf16* sQ = (bf16*)smem_raw;                       // 128 x 264
    bf16* sK = sQ + SBM * SPAD;                       // 256 x 264
    float* stagef = (float*)sK;                       // reused after compute: 128 x 260

    int bm = blockIdx.y * SBM;
    int bn = blockIdx.x * SBN;
    int tid = threadIdx.x;
    int warp = tid >> 5;
    int wr = warp >> 2;       // 0..1 -> 64 rows
    int wc = warp & 3;        // 0..3 -> 64 cols

    // load Q tile: 128 rows x 256 cols = 4096 float4
    #pragma unroll
    for (int rep = 0; rep < 16; rep++) {
        int idx = tid + rep * 256;
        int row = idx >> 5, g = idx & 31;
        *(float4*)(sQ + row * SPAD + g * 8) =
            *(const float4*)(g_qb + (size_t)(bm + row) * DKEY + g * 8);
    }
    // load K tile: 256 rows x 256 cols = 8192 float4
    #pragma unroll
    for (int rep = 0; rep < 32; rep++) {
        int idx = tid + rep * 256;
        int row = idx >> 5, g = idx & 31;
        *(float4*)(sK + row * SPAD + g * 8) =
            *(const float4*)(g_kb + (size_t)(bn + row) * DKEY + g * 8);
    }
    __syncthreads();

    wmma::fragment<wmma::accumulator, 16, 16, 16, float> acc[4][4];
    #pragma unroll
    for (int i = 0; i < 4; i++)
        #pragma unroll
        for (int j = 0; j < 4; j++) wmma::fill_fragment(acc[i][j], 0.0f);

    #pragma unroll
    for (int ks = 0; ks < DKEY / 16; ks++) {
        int kc = ks * 16;
        wmma::fragment<wmma::matrix_a, 16, 16, 16, bf16, wmma::row_major> a[4];
        wmma::fragment<wmma::matrix_b, 16, 16, 16, bf16, wmma::col_major> b[4];
        #pragma unroll
        for (int i = 0; i < 4; i++)
            wmma::load_matrix_sync(a[i], sQ + (wr * 64 + i * 16) * SPAD + kc, SPAD);
        #pragma unroll
        for (int j = 0; j < 4; j++)
            wmma::load_matrix_sync(b[j], sK + (wc * 64 + j * 16) * SPAD + kc, SPAD);
        #pragma unroll
        for (int i = 0; i < 4; i++)
            #pragma unroll
            for (int j = 0; j < 4; j++)
                wmma::mma_sync(acc[i][j], a[i], b[j], acc[i][j]);
    }
    __syncthreads();   // done reading sK; reuse as float stage

    #pragma unroll
    for (int i = 0; i < 4; i++)
        #pragma unroll
        for (int j = 0; j < 4; j++)
            wmma::store_matrix_sync(stagef + (wr * 64 + i * 16) * 260 + wc * 64 + j * 16,
                                    acc[i][j], 260, wmma::mem_row_major);
    __syncthreads();

    // cooperative convert + coalesced write: 128 rows x 32 groups of 8
    #pragma unroll
    for (int rep = 0; rep < 16; rep++) {
        int idx = tid + rep * 256;
        int row = idx >> 5, g = idx & 31;
        const float* src = stagef + row * 260 + g * 8;
        float4 f0 = *(const float4*)src;
        float4 f1 = *(const float4*)(src + 4);
        __align__(16) bf16 tmp[8];
        tmp[0] = __float2bfloat16(f0.x); tmp[1] = __float2bfloat16(f0.y);
        tmp[2] = __float2bfloat16(f0.z); tmp[3] = __float2bfloat16(f0.w);
        tmp[4] = __float2bfloat16(f1.x); tmp[5] = __float2bfloat16(f1.y);
        tmp[6] = __float2bfloat16(f1.z); tmp[7] = __float2bfloat16(f1.w);
        *(float4*)(g_sims + (size_t)(bm + row) * NMEM + bn + g * 8) = *(float4*)tmp;
    }
}

// ------------------------------ top-64 preselect (single DRAM pass, smem-resident row) ------------------------------
__device__ __forceinline__ unsigned ordkey16(unsigned u) {
    return (u & 0x8000u) ? (u ^ 0xFFFFu) : (u | 0x8000u);
}

__global__ __launch_bounds__(256) void topk_kernel() {
    int t = blockIdx.x;
    extern __shared__ unsigned short srow[];   // 32768 ordkeys = 64 KB
    __shared__ unsigned hist[256];
    __shared__ unsigned sh_b, sh_above, sh_K1, sh_thr;
    __shared__ unsigned ctrG, ctrE;
    int tid = threadIdx.x;

    const uint4* row4 = (const uint4*)(g_sims + (size_t)t * NMEM);
    hist[tid] = 0;
    __syncthreads();
    #pragma unroll
    for (int rep = 0; rep < 16; rep++) {
        int idx = tid + rep * 256;         // 0..4095 vec8 groups
        uint4 v = row4[idx];
        unsigned short k[8];
        k[0] = (unsigned short)ordkey16(v.x & 0xFFFFu);
        k[1] = (unsigned short)ordkey16(v.x >> 16);
        k[2] = (unsigned short)ordkey16(v.y & 0xFFFFu);
        k[3] = (unsigned short)ordkey16(v.y >> 16);
        k[4] = (unsigned short)ordkey16(v.z & 0xFFFFu);
        k[5] = (unsigned short)ordkey16(v.z >> 16);
        k[6] = (unsigned short)ordkey16(v.w & 0xFFFFu);
        k[7] = (unsigned short)ordkey16(v.w >> 16);
        #pragma unroll
        for (int e = 0; e < 8; e++) {
            srow[idx * 8 + e] = k[e];
            atomicAdd(&hist[k[e] >> 8], 1u);
        }
    }
    __syncthreads();
    if (tid == 0) {
        unsigned cum = 0; int b = 255;
        for (; b > 0; b--) { if (cum + hist[b] >= NCAND) break; cum += hist[b]; }
        sh_b = (unsigned)b; sh_above = cum;
    }
    __syncthreads();
    unsigned b = sh_b, above = sh_above;
    hist[tid] = 0;
    __syncthreads();
    for (int i = tid; i < NMEM; i += 256) {
        unsigned k = srow[i];
        if ((k >> 8) == b) atomicAdd(&hist[k & 255u], 1u);
    }
    __syncthreads();
    if (tid == 0) {
        unsigned cum = above; int l = 255;
        for (; l > 0; l--) { if (cum + hist[l] >= NCAND) break; cum += hist[l]; }
        sh_thr = (b << 8) | (unsigned)l;
        sh_K1 = cum;
        ctrG = 0; ctrE = 0;
    }
    __syncthreads();
    unsigned thr = sh_thr, K1 = sh_K1;
    for (int i = tid; i < NMEM; i += 256) {
        unsigned k = srow[i];
        if (k > thr) {
            unsigned p = atomicAdd(&ctrG, 1u);
            g_cand[t * NCAND + p] = i;
        } else if (k == thr) {
            unsigned p = atomicAdd(&ctrE, 1u);
            if (K1 + p < NCAND) g_cand[t * NCAND + K1 + p] = i;
        }
    }
}

// ------------------------------ exact double-float rescore + top-32 + softmax ------------------------------
__device__ __forceinline__ void kmac(float a, float b, float& s, float& c) {
    float p  = __fmul_rn(a, b);
    float e  = __fmaf_rn(a, b, -p);
    float t  = __fadd_rn(s, p);
    float bv = __fadd_rn(t, -s);
    float e1 = __fadd_rn(s, -__fadd_rn(t, -bv));
    float e2 = __fadd_rn(p, -bv);
    s = t;
    c = __fadd_rn(c, __fadd_rn(e, __fadd_rn(e1, e2)));
}

__global__ __launch_bounds__(256) void rescore_kernel() {
    int t = blockIdx.x;
    int tid = threadIdx.x;  // 256
    __shared__ __align__(16) float qhi[DKEY];
    __shared__ __align__(16) float qlo[DKEY];
    __shared__ float cval[NCAND];
    __shared__ int cidx[NCAND];
    __shared__ float sval[TOPK];
    __shared__ int sidx[TOPK];

    qhi[tid] = g_qn_hi[(size_t)t * DKEY + tid];
    qlo[tid] = g_qn_lo[(size_t)t * DKEY + tid];
    if (tid < NCAND) cidx[tid] = g_cand[t * NCAND + tid];
    __syncthreads();

    int c = tid >> 2, part = tid & 3;
    int ki = cidx[c];
    const float* khi = g_kn_hi + (size_t)ki * DKEY + part * 64;
    const float* klo = g_kn_lo + (size_t)ki * DKEY + part * 64;
    const float* qh = qhi + part * 64;
    const float* ql = qlo + part * 64;

    float s = 0.f, comp = 0.f, cr = 0.f;
    #pragma unroll 8
    for (int i = 0; i < 64; i++) {
        float kh = khi[i], kl = klo[i];
        float qhv = qh[i], qlv = ql[i];
        kmac(qhv, kh, s, comp);
        cr = __fmaf_rn(qhv, kl, cr);
        cr = __fmaf_rn(qlv, kh, cr);
    }
    double v = (double)s + (double)comp + (double)cr;
    v += __shfl_xor_sync(0xffffffffu, v, 1);
    v += __shfl_xor_sync(0xffffffffu, v, 2);
    if (part == 0) cval[c] = (float)v;
    __syncthreads();

    if (tid < NCAND) {
        float val = cval[tid]; int myi = cidx[tid];
        int rnk = 0;
        #pragma unroll 8
        for (int j = 0; j < NCAND; j++) {
            float u = cval[j];
            rnk += (u > val) || (u == val && cidx[j] < myi);
        }
        if (rnk < TOPK) { sval[rnk] = val; sidx[rnk] = myi; }
    }
    __syncthreads();

    if (tid < 32) {
        float val = sval[tid];
        float m = val;
        #pragma unroll
        for (int o = 16; o; o >>= 1) m = fmaxf(m, __shfl_xor_sync(0xffffffffu, m, o));
        float e = expf(val - m);
        float sum = e;
        #pragma unroll
        for (int o = 16; o; o >>= 1) sum += __shfl_xor_sync(0xffffffffu, sum, o);
        g_w[t * TOPK + tid] = e / sum;
        g_widx[t * TOPK + tid] = sidx[tid];
    }
}

// ------------------------------ weighted values gather ------------------------------
__global__ void gather_kernel(const float* __restrict__ values) {
    int t = blockIdx.x, tid = threadIdx.x;  // 256
    __shared__ float w[TOPK];
    __shared__ int idx[TOPK];
    if (tid < TOPK) { w[tid] = g_w[t * TOPK + tid]; idx[tid] = g_widx[t * TOPK + tid]; }
    __syncthreads();
    float4 acc = make_float4(0.f, 0.f, 0.f, 0.f);
    #pragma unroll 8
    for (int i = 0; i < TOPK; i++) {
        const float4 v = *((const float4*)(values + (size_t)idx[i] * DVAL) + tid);
        float wi = w[i];
        acc.x = fmaf(wi, v.x, acc.x);
        acc.y = fmaf(wi, v.y, acc.y);
        acc.z = fmaf(wi, v.z, acc.z);
        acc.w = fmaf(wi, v.w, acc.w);
    }
    ((float4*)(g_memout + (size_t)t * DVAL))[tid] = acc;
}

// ------------------------------ 3-term split-bf16 GEMM (gate / out) ------------------------------
template<int WHICH>
__global__ void gemm_kernel(float* __restrict__ Cout) {
    constexpr int N = (WHICH == 1) ? DVAL : DMODEL;
    constexpr int K = (WHICH == 2) ? DVAL : DMODEL;
    constexpr int BM = 128, BN = 64, KC = 16;

    const bf16* Ahi = (WHICH == 2) ? g_hhi : g_xhi;
    const bf16* Alo = (WHICH == 2) ? g_hlo : g_xlo;
    const bf16* Bhi = (WHICH == 1) ? g_wghi : g_wohi;
    const bf16* Blo = (WHICH == 1) ? g_wglo : g_wolo;

    extern __shared__ char smem_raw[];
    bf16* sAhi = (bf16*)smem_raw;
    bf16* sAlo = sAhi + BM * KC;
    bf16* sBhi = sAlo + BM * KC;
    bf16* sBlo = sBhi + BN * KC;
    float* stage = (float*)(sBlo + BN * KC);

    int bm = blockIdx.y * BM;
    int bn = blockIdx.x * BN;
    int tid = threadIdx.x;
    int warp = tid >> 5;
    int wr = warp >> 1;
    int wc = warp & 1;

    wmma::fragment<wmma::accumulator, 16, 16, 16, float> acc[2][2];
    #pragma unroll
    for (int i = 0; i < 2; i++)
        #pragma unroll
        for (int j = 0; j < 2; j++) wmma::fill_fragment(acc[i][j], 0.0f);

    int ar = tid >> 1, ah = (tid & 1) * 8;
    int br = (tid & 127) >> 1, bh2 = (tid & 1) * 8;

    for (int kc = 0; kc < K; kc += KC) {
        *(float4*)(sAhi + ar * KC + ah) = *(const float4*)(Ahi + (size_t)(bm + ar) * K + kc + ah);
        *(float4*)(sAlo + ar * KC + ah) = *(const float4*)(Alo + (size_t)(bm + ar) * K + kc + ah);
        if (tid < 128) {
            *(float4*)(sBhi + br * KC + bh2) = *(const float4*)(Bhi + (size_t)(bn + br) * K + kc + bh2);
            *(float4*)(sBlo + br * KC + bh2) = *(const float4*)(Blo + (size_t)(bn + br) * K + kc + bh2);
        }
        __syncthreads();

        wmma::fragment<wmma::matrix_a, 16, 16, 16, bf16, wmma::row_major> a0, a1, c0, c1;
        wmma::fragment<wmma::matrix_b, 16, 16, 16, bf16, wmma::col_major> b0, b1;

        wmma::load_matrix_sync(a0, sAhi + (wr * 32 + 0) * KC, KC);
        wmma::load_matrix_sync(a1, sAhi + (wr * 32 + 16) * KC, KC);
        wmma::load_matrix_sync(b0, sBhi + (wc * 32 + 0) * KC, KC);
        wmma::load_matrix_sync(b1, sBhi + (wc * 32 + 16) * KC, KC);
        wmma::mma_sync(acc[0][0], a0, b0, acc[0][0]);
        wmma::mma_sync(acc[0][1], a0, b1, acc[0][1]);
        wmma::mma_sync(acc[1][0], a1, b0, acc[1][0]);
        wmma::mma_sync(acc[1][1], a1, b1, acc[1][1]);

        wmma::load_matrix_sync(c0, sAlo + (wr * 32 + 0) * KC, KC);
        wmma::load_matrix_sync(c1, sAlo + (wr * 32 + 16) * KC, KC);
        wmma::mma_sync(acc[0][0], c0, b0, acc[0][0]);
        wmma::mma_sync(acc[0][1], c0, b1, acc[0][1]);
        wmma::mma_sync(acc[1][0], c1, b0, acc[1][0]);
        wmma::mma_sync(acc[1][1], c1, b1, acc[1][1]);

        wmma::load_matrix_sync(b0, sBlo + (wc * 32 + 0) * KC, KC);
        wmma::load_matrix_sync(b1, sBlo + (wc * 32 + 16) * KC, KC);
        wmma::mma_sync(acc[0][0], a0, b0, acc[0][0]);
        wmma::mma_sync(acc[0][1], a0, b1, acc[0][1]);
        wmma::mma_sync(acc[1][0], a1, b0, acc[1][0]);
        wmma::mma_sync(acc[1][1], a1, b1, acc[1][1]);

        __syncthreads();
    }

    if (WHICH == 2) {
        #pragma unroll
        for (int i = 0; i < 2; i++)
            #pragma unroll
            for (int j = 0; j < 2; j++)
                wmma::store_matrix_sync(Cout + (size_t)(bm + wr * 32 + i * 16) * N + bn + wc * 32 + j * 16,
                                        acc[i][j], N, wmma::mem_row_major);
    } else {
        #pragma unroll
        for (int i = 0; i < 2; i++)
            #pragma unroll
            for (int j = 0; j < 2; j++)
                wmma::store_matrix_sync(stage + (wr * 32 + i * 16) * 68 + wc * 32 + j * 16,
                                        acc[i][j], 68, wmma::mem_row_major);
        __syncthreads();
        for (int e = tid; e < BM * BN; e += 256) {
            int lr = e >> 6, lc = e & 63;
            float gpre = stage[lr * 68 + lc];
            float sg = gpre / (1.0f + expf(-gpre));
            size_t gi = (size_t)(bm + lr) * N + bn + lc;
            float h = sg * g_memout[gi];
            bf16 hh = __float2bfloat16(h);
            g_hhi[gi] = hh;
            g_hlo[gi] = __float2bfloat16(h - __bfloat162float(hh));
        }
    }
}

// ------------------------------ launcher ------------------------------
extern "C" void kernel_launch(void* const* d_in, const int* in_sizes, int n_in,
                              void* d_out, int out_size) {
    const float *x = nullptr, *keys = nullptr, *values = nullptr,
                *w_q = nullptr, *w_gate = nullptr, *w_out = nullptr;
    for (int i = 0; i < n_in; i++) {
        int sz = in_sizes[i];
        const float* p = (const float*)d_in[i];
        if (sz == BS_TOK * DMODEL)      x = p;
        else if (sz == NMEM * DKEY)     keys = p;
        else if (sz == NMEM * DVAL)     values = p;
        else if (sz == DKEY * DMODEL)   w_q = p;
        else if (sz == DVAL * DMODEL) { if (!w_gate) w_gate = p; else w_out = p; }
    }
    float* out = (float*)d_out;

    cudaFuncSetAttribute(sims_kernel, cudaFuncAttributeMaxDynamicSharedMemorySize, SIMS_SMEM);
    cudaFuncSetAttribute(topk_kernel, cudaFuncAttributeMaxDynamicSharedMemorySize, NMEM * 2);

    // 1. merged splits for gate/out GEMMs
    splitall_kernel<<<(NX + NWG + NWO + 255) / 256, 256>>>(x, w_gate, w_out);

    // 2. normalize keys (double-float fp32)
    knorm_kernel<<<NMEM / 8, 256>>>(keys);

    // 3. exact q = x @ w_q^T (offset-accumulator compensated fp32)
    qexact_kernel<<<dim3(DKEY / QTN, BS_TOK / QTM), 256>>>(x, w_q);

    // 4. normalize q (fp64, small)
    qnorm_kernel<<<BS_TOK / 8, 256>>>();

    // 5. sims (bf16 preselect, full-K smem-resident)
    sims_kernel<<<dim3(NMEM / SBN, BS_TOK / SBM), 256, SIMS_SMEM>>>();

    // 6. top-64 preselect (single DRAM pass)
    topk_kernel<<<BS_TOK, 256, NMEM * 2>>>();

    // 7. exact rescore + top-32 + softmax
    rescore_kernel<<<BS_TOK, 256>>>();

    // 8. mem_out gather
    gather_kernel<<<BS_TOK, 256>>>(values);

    size_t smem_g = (size_t)(128 * 16 + 128 * 16 + 64 * 16 + 64 * 16) * sizeof(bf16);
    size_t smem_g1 = smem_g + (size_t)128 * 68 * sizeof(float);

    // 9. gate = silu(x @ w_gate^T); h = gate * mem_out -> h hi/lo
    gemm_kernel<1><<<dim3(DVAL / 64, BS_TOK / 128), 256, smem_g1>>>(nullptr);

    // 10. out = h @ w_out^T -> d_out
    gemm_kernel<2><<<dim3(DMODEL / 64, BS_TOK / 128), 256, smem_g>>>(out);
}